// round 4
// baseline (speedup 1.0000x reference)
#include <cuda_runtime.h>
#include <cstdint>

// FeatureDictionary: fused codebook gather + barycentric interp + normal.
//  0 coords    [B,S,3]   f32
//  1 idx       [B]       i32
//  2 smpl_F    [13776,3] i32
//  3 fid       [B,S]     i32
//  4 weights   [B,S,3]   f32
//  5 sdf       [B,S,1]   f32
//  6 hitpt     [B,S,3]   f32
//  7 codebooks [256,6890,64] f32
// Output: concat( weighted_feats [B,S,64], coords_feats [B,S,3], normal [B,S,3] )

#define NUM_VERTICES 6890
#define DFEAT 64

struct PointCtx {
    const float4* r0;
    const float4* r1;
    const float4* r2;
    float w0, w1, w2;
};

__device__ __forceinline__ void load_ctx(PointCtx& c,
                                         const float* __restrict__ cb,
                                         const int*   __restrict__ smpl_F,
                                         const int*   __restrict__ fid,
                                         const float* __restrict__ weights,
                                         int p, int lane)
{
    int f  = __ldg(fid + p);
    int v0 = __ldg(smpl_F + 3 * f + 0);
    int v1 = __ldg(smpl_F + 3 * f + 1);
    int v2 = __ldg(smpl_F + 3 * f + 2);
    c.w0 = __ldg(weights + 3 * p + 0);
    c.w1 = __ldg(weights + 3 * p + 1);
    c.w2 = __ldg(weights + 3 * p + 2);
    c.r0 = (const float4*)(cb + (size_t)v0 * DFEAT) + lane;
    c.r1 = (const float4*)(cb + (size_t)v1 * DFEAT) + lane;
    c.r2 = (const float4*)(cb + (size_t)v2 * DFEAT) + lane;
}

__device__ __forceinline__ void write_tail(float* __restrict__ out,
                                           const float* __restrict__ coords,
                                           const float* __restrict__ hitpt,
                                           const float* __restrict__ sdf,
                                           float w1, float w2,
                                           int p, int lane, size_t C_OFF, size_t N_OFF)
{
    if (lane == 0) {
        float cx = __ldg(coords + 3 * p + 0);
        float cy = __ldg(coords + 3 * p + 1);
        float cz = __ldg(coords + 3 * p + 2);
        float hx = __ldg(hitpt  + 3 * p + 0);
        float hy = __ldg(hitpt  + 3 * p + 1);
        float hz = __ldg(hitpt  + 3 * p + 2);
        float dx = hx - cx, dy = hy - cy, dz = hz - cz;
        float nrm = sqrtf(dx * dx + dy * dy + dz * dz);
        float inv = 1.0f / fmaxf(nrm, 1e-6f);
        out[N_OFF + 3 * (size_t)p + 0] = dx * inv;
        out[N_OFF + 3 * (size_t)p + 1] = dy * inv;
        out[N_OFF + 3 * (size_t)p + 2] = dz * inv;
    } else if (lane == 1) {
        out[C_OFF + 3 * (size_t)p + 0] = w1;
        out[C_OFF + 3 * (size_t)p + 1] = w2;
        out[C_OFF + 3 * (size_t)p + 2] = __ldg(sdf + p);
    }
}

__global__ __launch_bounds__(256)
void feature_dict_kernel(const float* __restrict__ coords,
                         const int*   __restrict__ idx,
                         const int*   __restrict__ smpl_F,
                         const int*   __restrict__ fid,
                         const float* __restrict__ weights,
                         const float* __restrict__ sdf,
                         const float* __restrict__ hitpt,
                         const float* __restrict__ codebooks,
                         float*       __restrict__ out,
                         int BS, int S)
{
    // Warp = 4 slots x 8 lanes. Each slot handles 2 points: g*8+slot, g*8+slot+4.
    int t    = blockIdx.x * blockDim.x + threadIdx.x;
    int g    = t >> 5;            // warp id within batch row
    int slot = (t >> 3) & 3;
    int lane = t & 7;             // 8 float4 chunks of 64-f32 row -> full 128B lines

    int ps0 = g * 8 + slot;       // point within batch row
    int ps1 = ps0 + 4;
    if (ps0 >= S) return;

    int b  = blockIdx.y;
    int pA = b * S + ps0;
    int pB = b * S + ps1;
    bool hasB = (ps1 < S);

    int subj = __ldg(idx + b);
    const float* cb = codebooks + (size_t)subj * (NUM_VERTICES * DFEAT);

    PointCtx A, Bc;
    load_ctx(A, cb, smpl_F, fid, weights, pA, lane);
    if (hasB) load_ctx(Bc, cb, smpl_F, fid, weights, pB, lane);

    // 12 independent gather loads in flight (6 per point).
    float4 a0 = __ldg(A.r0);
    float4 a1 = __ldg(A.r0 + 8);
    float4 c0 = __ldg(A.r1);
    float4 c1 = __ldg(A.r1 + 8);
    float4 d0 = __ldg(A.r2);
    float4 d1 = __ldg(A.r2 + 8);

    float4 e0, e1, f0, f1, g0, g1;
    if (hasB) {
        e0 = __ldg(Bc.r0);
        e1 = __ldg(Bc.r0 + 8);
        f0 = __ldg(Bc.r1);
        f1 = __ldg(Bc.r1 + 8);
        g0 = __ldg(Bc.r2);
        g1 = __ldg(Bc.r2 + 8);
    }

    size_t C_OFF = (size_t)BS * DFEAT;
    size_t N_OFF = C_OFF + (size_t)BS * 3;

    // Point A compute + store
    {
        float w0 = A.w0, w1 = A.w1, w2 = A.w2;
        float4 o0, o1;
        o0.x = w0*a0.x + w1*c0.x + w2*d0.x;  o0.y = w0*a0.y + w1*c0.y + w2*d0.y;
        o0.z = w0*a0.z + w1*c0.z + w2*d0.z;  o0.w = w0*a0.w + w1*c0.w + w2*d0.w;
        o1.x = w0*a1.x + w1*c1.x + w2*d1.x;  o1.y = w0*a1.y + w1*c1.y + w2*d1.y;
        o1.z = w0*a1.z + w1*c1.z + w2*d1.z;  o1.w = w0*a1.w + w1*c1.w + w2*d1.w;
        float4* outv = (float4*)out + (size_t)pA * (DFEAT / 4) + lane;
        outv[0] = o0;
        outv[8] = o1;
        write_tail(out, coords, hitpt, sdf, w1, w2, pA, lane, C_OFF, N_OFF);
    }

    // Point B compute + store
    if (hasB) {
        float w0 = Bc.w0, w1 = Bc.w1, w2 = Bc.w2;
        float4 o0, o1;
        o0.x = w0*e0.x + w1*f0.x + w2*g0.x;  o0.y = w0*e0.y + w1*f0.y + w2*g0.y;
        o0.z = w0*e0.z + w1*f0.z + w2*g0.z;  o0.w = w0*e0.w + w1*f0.w + w2*g0.w;
        o1.x = w0*e1.x + w1*f1.x + w2*g1.x;  o1.y = w0*e1.y + w1*f1.y + w2*g1.y;
        o1.z = w0*e1.z + w1*f1.z + w2*g1.z;  o1.w = w0*e1.w + w1*f1.w + w2*g1.w;
        float4* outv = (float4*)out + (size_t)pB * (DFEAT / 4) + lane;
        outv[0] = o0;
        outv[8] = o1;
        write_tail(out, coords, hitpt, sdf, w1, w2, pB, lane, C_OFF, N_OFF);
    }
}

extern "C" void kernel_launch(void* const* d_in, const int* in_sizes, int n_in,
                              void* d_out, int out_size)
{
    const float* coords    = (const float*)d_in[0];
    const int*   idx       = (const int*)  d_in[1];
    const int*   smpl_F    = (const int*)  d_in[2];
    const int*   fid       = (const int*)  d_in[3];
    const float* weights   = (const float*)d_in[4];
    const float* sdf       = (const float*)d_in[5];
    const float* hitpt     = (const float*)d_in[6];
    const float* codebooks = (const float*)d_in[7];
    float*       out       = (float*)d_out;

    int BS = in_sizes[3];       // B*S
    int B  = in_sizes[1];       // batch
    int S  = BS / B;

    // One warp handles 8 points -> S/8 warps per batch row.
    int threads = 256;
    long long warps_per_row = (S + 7) / 8;
    long long thr_per_row   = warps_per_row * 32;
    dim3 grid((unsigned)((thr_per_row + threads - 1) / threads), B);

    feature_dict_kernel<<<grid, threads>>>(
        coords, idx, smpl_F, fid, weights, sdf, hitpt, codebooks,
        out, BS, S);
}

// round 5
// speedup vs baseline: 1.1030x; 1.1030x over previous
#include <cuda_runtime.h>
#include <cstdint>

// FeatureDictionary: fused codebook gather + barycentric interp + normal.
//  0 coords    [B,S,3]   f32
//  1 idx       [B]       i32
//  2 smpl_F    [13776,3] i32
//  3 fid       [B,S]     i32
//  4 weights   [B,S,3]   f32
//  5 sdf       [B,S,1]   f32
//  6 hitpt     [B,S,3]   f32
//  7 codebooks [256,6890,64] f32
// Output: concat( weighted_feats [B,S,64], coords_feats [B,S,3], normal [B,S,3] )

#define NUM_VERTICES 6890
#define DFEAT 64

__global__ __launch_bounds__(256)
void feature_dict_kernel(const float* __restrict__ coords,
                         const int*   __restrict__ idx,
                         const int*   __restrict__ smpl_F,
                         const int*   __restrict__ fid,
                         const float* __restrict__ weights,
                         const float* __restrict__ sdf,
                         const float* __restrict__ hitpt,
                         const float* __restrict__ codebooks,
                         float*       __restrict__ out,
                         int BS, int S)
{
    // 8 lanes per point (full 128B lines); blockIdx.y = batch index.
    int t    = blockIdx.x * blockDim.x + threadIdx.x;
    int ps   = t >> 3;            // point index within batch row
    int lane = t & 7;
    if (ps >= S) return;
    unsigned mask = __activemask();

    int b = blockIdx.y;
    int p = b * S + ps;

    int subj = __ldg(idx + b);
    const float* cb = codebooks + (size_t)subj * (NUM_VERTICES * DFEAT);

    int f = __ldg(fid + p);

    // Lane-split scalar loads + width-8 shuffles (replaces 12 scalar LDGs
    // with 3 LDGs; removes all divergent branches).
    // L1: lanes 0-2 -> smpl_F[3f+lane]
    int vraw = __ldg(smpl_F + 3 * f + (lane < 2 ? lane : 2));
    int v0 = __shfl_sync(mask, vraw, 0, 8);
    int v1 = __shfl_sync(mask, vraw, 1, 8);
    int v2 = __shfl_sync(mask, vraw, 2, 8);

    // L2: lanes 0-2 -> weights[3p+lane], lane 3 -> sdf[p]
    const float* srcW = (lane < 3) ? (weights + 3 * p + lane) : (sdf + p);
    float wraw = __ldg(srcW);
    float w0   = __shfl_sync(mask, wraw, 0, 8);
    float w1   = __shfl_sync(mask, wraw, 1, 8);
    float w2   = __shfl_sync(mask, wraw, 2, 8);
    float sdfv = __shfl_sync(mask, wraw, 3, 8);

    // L3: lanes 0-2 -> coords[3p+lane], lanes 3-5 -> hitpt[3p+lane-3]
    const float* srcC = (lane < 3) ? (coords + 3 * p + lane)
                 : (lane < 6) ? (hitpt + 3 * p + (lane - 3))
                              : (sdf + p);
    float craw = __ldg(srcC);

    // Gather: 6 independent 128B-line loads in flight.
    const float4* r0 = (const float4*)(cb + (size_t)v0 * DFEAT) + lane;
    const float4* r1 = (const float4*)(cb + (size_t)v1 * DFEAT) + lane;
    const float4* r2 = (const float4*)(cb + (size_t)v2 * DFEAT) + lane;

    float4 a0 = __ldg(r0);
    float4 a1 = __ldg(r0 + 8);
    float4 c0 = __ldg(r1);
    float4 c1 = __ldg(r1 + 8);
    float4 d0 = __ldg(r2);
    float4 d1 = __ldg(r2 + 8);

    // Tail math (all lanes, redundant but branch-free).
    float dx = __shfl_sync(mask, craw, 3, 8) - __shfl_sync(mask, craw, 0, 8);
    float dy = __shfl_sync(mask, craw, 4, 8) - __shfl_sync(mask, craw, 1, 8);
    float dz = __shfl_sync(mask, craw, 5, 8) - __shfl_sync(mask, craw, 2, 8);
    float nrm = sqrtf(dx * dx + dy * dy + dz * dz);
    float inv = 1.0f / fmaxf(nrm, 1e-6f);

    float4 o0, o1;
    o0.x = w0*a0.x + w1*c0.x + w2*d0.x;  o0.y = w0*a0.y + w1*c0.y + w2*d0.y;
    o0.z = w0*a0.z + w1*c0.z + w2*d0.z;  o0.w = w0*a0.w + w1*c0.w + w2*d0.w;
    o1.x = w0*a1.x + w1*c1.x + w2*d1.x;  o1.y = w0*a1.y + w1*c1.y + w2*d1.y;
    o1.z = w0*a1.z + w1*c1.z + w2*d1.z;  o1.w = w0*a1.w + w1*c1.w + w2*d1.w;

    float4* outv = (float4*)out + (size_t)p * (DFEAT / 4) + lane;
    outv[0] = o0;
    outv[8] = o1;

    // Lane-mapped tail store: lanes 0-2 -> normal, lanes 3-5 -> coords_feats.
    size_t C_OFF = (size_t)BS * DFEAT;
    size_t N_OFF = C_OFF + (size_t)BS * 3;

    float ov = (lane == 0) ? dx * inv
             : (lane == 1) ? dy * inv
             : (lane == 2) ? dz * inv
             : (lane == 3) ? w1
             : (lane == 4) ? w2
             :               sdfv;
    size_t oaddr = (lane < 3) ? (N_OFF + 3 * (size_t)p + lane)
                              : (C_OFF + 3 * (size_t)p + (lane - 3));
    if (lane < 6) out[oaddr] = ov;
}

extern "C" void kernel_launch(void* const* d_in, const int* in_sizes, int n_in,
                              void* d_out, int out_size)
{
    const float* coords    = (const float*)d_in[0];
    const int*   idx       = (const int*)  d_in[1];
    const int*   smpl_F    = (const int*)  d_in[2];
    const int*   fid       = (const int*)  d_in[3];
    const float* weights   = (const float*)d_in[4];
    const float* sdf       = (const float*)d_in[5];
    const float* hitpt     = (const float*)d_in[6];
    const float* codebooks = (const float*)d_in[7];
    float*       out       = (float*)d_out;

    int BS = in_sizes[3];       // B*S
    int B  = in_sizes[1];       // batch
    int S  = BS / B;

    int threads = 256;
    long long thr_per_row = (long long)S * 8;
    dim3 grid((unsigned)((thr_per_row + threads - 1) / threads), B);

    feature_dict_kernel<<<grid, threads>>>(
        coords, idx, smpl_F, fid, weights, sdf, hitpt, codebooks,
        out, BS, S);
}

// round 6
// speedup vs baseline: 1.2305x; 1.1155x over previous
#include <cuda_runtime.h>
#include <cstdint>

// FeatureDictionary: fused codebook gather + barycentric interp + normal.
// R6 = R2 (best: 55.6us, 32 regs, 92% occ) + cache-policy hints:
//   - __ldcs on read-once streaming inputs (don't pollute L1)
//   - __stcs on write-once outputs (evict-first; keep L1 for codebook gathers)
//  0 coords    [B,S,3]   f32
//  1 idx       [B]       i32
//  2 smpl_F    [13776,3] i32
//  3 fid       [B,S]     i32
//  4 weights   [B,S,3]   f32
//  5 sdf       [B,S,1]   f32
//  6 hitpt     [B,S,3]   f32
//  7 codebooks [256,6890,64] f32
// Output: concat( weighted_feats [B,S,64], coords_feats [B,S,3], normal [B,S,3] )

#define NUM_VERTICES 6890
#define DFEAT 64

__global__ __launch_bounds__(256)
void feature_dict_kernel(const float* __restrict__ coords,
                         const int*   __restrict__ idx,
                         const int*   __restrict__ smpl_F,
                         const int*   __restrict__ fid,
                         const float* __restrict__ weights,
                         const float* __restrict__ sdf,
                         const float* __restrict__ hitpt,
                         const float* __restrict__ codebooks,
                         float*       __restrict__ out,
                         int BS, int S)
{
    // 8 lanes per point; blockIdx.y = batch index (no integer division).
    int t    = blockIdx.x * blockDim.x + threadIdx.x;
    int ps   = t >> 3;            // point index within batch row
    int lane = t & 7;             // 2 float4 feature chunks per lane
    if (ps >= S) return;

    int b = blockIdx.y;
    int p = b * S + ps;           // global point index

    // Subject codebook base: uniform per block.
    int subj = __ldg(idx + b);
    const float* cb = codebooks + (size_t)subj * (NUM_VERTICES * DFEAT);

    // Streaming (read-once) scalars: evict-first so they don't displace
    // codebook lines in L1.
    int f  = __ldcs(fid + p);
    int v0 = __ldg(smpl_F + 3 * f + 0);   // smpl_F is tiny & hot: keep cached
    int v1 = __ldg(smpl_F + 3 * f + 1);
    int v2 = __ldg(smpl_F + 3 * f + 2);

    float w0 = __ldcs(weights + 3 * p + 0);
    float w1 = __ldcs(weights + 3 * p + 1);
    float w2 = __ldcs(weights + 3 * p + 2);

    // 256B codebook rows, float4-aligned. Each lane loads chunks lane, lane+8
    // -> full 128B lines per warp-quarter. These are the latency-critical
    // loads: default caching (L1-allocate).
    const float4* r0 = (const float4*)(cb + (size_t)v0 * DFEAT);
    const float4* r1 = (const float4*)(cb + (size_t)v1 * DFEAT);
    const float4* r2 = (const float4*)(cb + (size_t)v2 * DFEAT);

    // 6 independent loads in flight.
    float4 a0 = __ldg(r0 + lane);
    float4 c0 = __ldg(r1 + lane);
    float4 d0 = __ldg(r2 + lane);
    float4 a1 = __ldg(r0 + lane + 8);
    float4 c1 = __ldg(r1 + lane + 8);
    float4 d1 = __ldg(r2 + lane + 8);

    float4 o0, o1;
    o0.x = w0 * a0.x + w1 * c0.x + w2 * d0.x;
    o0.y = w0 * a0.y + w1 * c0.y + w2 * d0.y;
    o0.z = w0 * a0.z + w1 * c0.z + w2 * d0.z;
    o0.w = w0 * a0.w + w1 * c0.w + w2 * d0.w;
    o1.x = w0 * a1.x + w1 * c1.x + w2 * d1.x;
    o1.y = w0 * a1.y + w1 * c1.y + w2 * d1.y;
    o1.z = w0 * a1.z + w1 * c1.z + w2 * d1.z;
    o1.w = w0 * a1.w + w1 * c1.w + w2 * d1.w;

    float4* outv = (float4*)out + (size_t)p * (DFEAT / 4);
    __stcs(outv + lane,     o0);
    __stcs(outv + lane + 8, o1);

    if (lane == 0) {
        // normal
        size_t C_OFF = (size_t)BS * DFEAT;
        size_t N_OFF = C_OFF + (size_t)BS * 3;
        float cx = __ldcs(coords + 3 * p + 0);
        float cy = __ldcs(coords + 3 * p + 1);
        float cz = __ldcs(coords + 3 * p + 2);
        float hx = __ldcs(hitpt  + 3 * p + 0);
        float hy = __ldcs(hitpt  + 3 * p + 1);
        float hz = __ldcs(hitpt  + 3 * p + 2);
        float dx = hx - cx, dy = hy - cy, dz = hz - cz;
        float nrm = sqrtf(dx * dx + dy * dy + dz * dz);
        float inv = 1.0f / fmaxf(nrm, 1e-6f);
        __stcs(out + N_OFF + 3 * (size_t)p + 0, dx * inv);
        __stcs(out + N_OFF + 3 * (size_t)p + 1, dy * inv);
        __stcs(out + N_OFF + 3 * (size_t)p + 2, dz * inv);
    } else if (lane == 1) {
        // coords_feats = [w1, w2, sdf]
        size_t C_OFF = (size_t)BS * DFEAT;
        __stcs(out + C_OFF + 3 * (size_t)p + 0, w1);
        __stcs(out + C_OFF + 3 * (size_t)p + 1, w2);
        __stcs(out + C_OFF + 3 * (size_t)p + 2, __ldcs(sdf + p));
    }
}

extern "C" void kernel_launch(void* const* d_in, const int* in_sizes, int n_in,
                              void* d_out, int out_size)
{
    const float* coords    = (const float*)d_in[0];
    const int*   idx       = (const int*)  d_in[1];
    const int*   smpl_F    = (const int*)  d_in[2];
    const int*   fid       = (const int*)  d_in[3];
    const float* weights   = (const float*)d_in[4];
    const float* sdf       = (const float*)d_in[5];
    const float* hitpt     = (const float*)d_in[6];
    const float* codebooks = (const float*)d_in[7];
    float*       out       = (float*)d_out;

    int BS = in_sizes[3];       // B*S
    int B  = in_sizes[1];       // batch
    int S  = BS / B;

    int threads = 256;
    dim3 grid((S * 8 + threads - 1) / threads, B);

    feature_dict_kernel<<<grid, threads>>>(
        coords, idx, smpl_F, fid, weights, sdf, hitpt, codebooks,
        out, BS, S);
}

// round 7
// speedup vs baseline: 1.4596x; 1.1862x over previous
#include <cuda_runtime.h>
#include <cstdint>

// FeatureDictionary, two-kernel split:
//   A: codebook gather + barycentric interp   (latency-critical, 32 regs)
//   B: normal + coords_feats streaming tail   (bandwidth-trivial, coalesced)
//  0 coords    [B,S,3]   f32
//  1 idx       [B]       i32
//  2 smpl_F    [13776,3] i32
//  3 fid       [B,S]     i32
//  4 weights   [B,S,3]   f32
//  5 sdf       [B,S,1]   f32
//  6 hitpt     [B,S,3]   f32
//  7 codebooks [256,6890,64] f32
// Output: concat( weighted_feats [B,S,64], coords_feats [B,S,3], normal [B,S,3] )

#define NUM_VERTICES 6890
#define DFEAT 64

__global__ __launch_bounds__(256)
void feature_gather_kernel(const int*   __restrict__ idx,
                           const int*   __restrict__ smpl_F,
                           const int*   __restrict__ fid,
                           const float* __restrict__ weights,
                           const float* __restrict__ codebooks,
                           float*       __restrict__ out,
                           int S)
{
    // 8 lanes per point; blockIdx.y = batch index.
    int t    = blockIdx.x * blockDim.x + threadIdx.x;
    int ps   = t >> 3;            // point index within batch row
    int lane = t & 7;
    if (ps >= S) return;

    int b = blockIdx.y;
    int p = b * S + ps;

    int subj = __ldg(idx + b);
    const float* cb = codebooks + (size_t)subj * (NUM_VERTICES * DFEAT);

    int f  = __ldcs(fid + p);
    int v0 = __ldg(smpl_F + 3 * f + 0);
    int v1 = __ldg(smpl_F + 3 * f + 1);
    int v2 = __ldg(smpl_F + 3 * f + 2);

    float w0 = __ldcs(weights + 3 * p + 0);
    float w1 = __ldcs(weights + 3 * p + 1);
    float w2 = __ldcs(weights + 3 * p + 2);

    const float4* r0 = (const float4*)(cb + (size_t)v0 * DFEAT);
    const float4* r1 = (const float4*)(cb + (size_t)v1 * DFEAT);
    const float4* r2 = (const float4*)(cb + (size_t)v2 * DFEAT);

    // 6 independent 128B-line loads in flight.
    float4 a0 = __ldg(r0 + lane);
    float4 c0 = __ldg(r1 + lane);
    float4 d0 = __ldg(r2 + lane);
    float4 a1 = __ldg(r0 + lane + 8);
    float4 c1 = __ldg(r1 + lane + 8);
    float4 d1 = __ldg(r2 + lane + 8);

    float4 o0, o1;
    o0.x = w0 * a0.x + w1 * c0.x + w2 * d0.x;
    o0.y = w0 * a0.y + w1 * c0.y + w2 * d0.y;
    o0.z = w0 * a0.z + w1 * c0.z + w2 * d0.z;
    o0.w = w0 * a0.w + w1 * c0.w + w2 * d0.w;
    o1.x = w0 * a1.x + w1 * c1.x + w2 * d1.x;
    o1.y = w0 * a1.y + w1 * c1.y + w2 * d1.y;
    o1.z = w0 * a1.z + w1 * c1.z + w2 * d1.z;
    o1.w = w0 * a1.w + w1 * c1.w + w2 * d1.w;

    float4* outv = (float4*)out + (size_t)p * (DFEAT / 4);
    __stcs(outv + lane,     o0);
    __stcs(outv + lane + 8, o1);
}

__global__ __launch_bounds__(256)
void tail_kernel(const float* __restrict__ coords,
                 const float* __restrict__ weights,
                 const float* __restrict__ sdf,
                 const float* __restrict__ hitpt,
                 float*       __restrict__ out,
                 int BS, int S)
{
    int ps = blockIdx.x * blockDim.x + threadIdx.x;
    if (ps >= S) return;
    int b = blockIdx.y;
    int p = b * S + ps;

    size_t C_OFF = (size_t)BS * DFEAT;
    size_t N_OFF = C_OFF + (size_t)BS * 3;

    float cx = __ldcs(coords + 3 * p + 0);
    float cy = __ldcs(coords + 3 * p + 1);
    float cz = __ldcs(coords + 3 * p + 2);
    float hx = __ldcs(hitpt  + 3 * p + 0);
    float hy = __ldcs(hitpt  + 3 * p + 1);
    float hz = __ldcs(hitpt  + 3 * p + 2);
    float w1 = __ldcs(weights + 3 * p + 1);
    float w2 = __ldcs(weights + 3 * p + 2);
    float sd = __ldcs(sdf + p);

    float dx = hx - cx, dy = hy - cy, dz = hz - cz;
    float nrm = sqrtf(dx * dx + dy * dy + dz * dz);
    float inv = 1.0f / fmaxf(nrm, 1e-6f);

    __stcs(out + N_OFF + 3 * (size_t)p + 0, dx * inv);
    __stcs(out + N_OFF + 3 * (size_t)p + 1, dy * inv);
    __stcs(out + N_OFF + 3 * (size_t)p + 2, dz * inv);

    __stcs(out + C_OFF + 3 * (size_t)p + 0, w1);
    __stcs(out + C_OFF + 3 * (size_t)p + 1, w2);
    __stcs(out + C_OFF + 3 * (size_t)p + 2, sd);
}

extern "C" void kernel_launch(void* const* d_in, const int* in_sizes, int n_in,
                              void* d_out, int out_size)
{
    const float* coords    = (const float*)d_in[0];
    const int*   idx       = (const int*)  d_in[1];
    const int*   smpl_F    = (const int*)  d_in[2];
    const int*   fid       = (const int*)  d_in[3];
    const float* weights   = (const float*)d_in[4];
    const float* sdf       = (const float*)d_in[5];
    const float* hitpt     = (const float*)d_in[6];
    const float* codebooks = (const float*)d_in[7];
    float*       out       = (float*)d_out;

    int BS = in_sizes[3];       // B*S
    int B  = in_sizes[1];       // batch
    int S  = BS / B;

    int threads = 256;
    dim3 gridA((S * 8 + threads - 1) / threads, B);
    feature_gather_kernel<<<gridA, threads>>>(
        idx, smpl_F, fid, weights, codebooks, out, S);

    dim3 gridB((S + threads - 1) / threads, B);
    tail_kernel<<<gridB, threads>>>(
        coords, weights, sdf, hitpt, out, BS, S);
}